// round 16
// baseline (speedup 1.0000x reference)
#include <cuda_runtime.h>
#include <cstdint>

#define NUM_SRC 16384
#define NUM_DST 8192
#define N_NBR 50
#define D_FEAT 64
#define K_SEL 10
#define TOTAL_IDX (NUM_DST * N_NBR)
#define PIPE_GRID 152
#define ROW_BYTES (NUM_SRC * 4)   // 64 KB
#define NSTAGE 3
#define USE_CAP 96
#define PIPE_WARPS 16

#define WPITCH 52
#define W_TILE 2600
#define W_CACHE (W_TILE)
#define W_SELS  (W_TILE + 56)
#define W_SIDX  (W_TILE + 66)
#define W_NRMK  (W_TILE + 76)
#define W_STRIDE 2688               // floats, 10752 B

__device__ int   g_deg[NUM_SRC];
__device__ int   g_idx[TOTAL_IDX];
__device__ int   g_uses[NUM_SRC * USE_CAP];
__device__ float g_tile[(size_t)NUM_DST * N_NBR * WPITCH];  // 85 MB, pitch-52 tiles
__device__ int   g_is64;

__device__ __forceinline__ uint32_t smem_u32(const void* p) {
    uint32_t a;
    asm("{ .reg .u64 t; cvta.to.shared.u64 t, %1; cvt.u32.u64 %0, t; }" : "=r"(a) : "l"(p));
    return a;
}
__device__ __forceinline__ void mbar_init(uint32_t mbar, uint32_t cnt) {
    asm volatile("mbarrier.init.shared.b64 [%0], %1;" :: "r"(mbar), "r"(cnt) : "memory");
}
__device__ __forceinline__ void mbar_expect_tx(uint32_t mbar, uint32_t bytes) {
    asm volatile("mbarrier.arrive.expect_tx.shared.b64 _, [%0], %1;" :: "r"(mbar), "r"(bytes) : "memory");
}
__device__ __forceinline__ void mbar_wait(uint32_t mbar, uint32_t parity) {
    uint32_t done;
    asm volatile(
        "{ .reg .pred p;\n"
        "mbarrier.try_wait.parity.acquire.cta.shared::cta.b64 p, [%1], %2;\n"
        "selp.b32 %0, 1, 0, p; }"
        : "=r"(done) : "r"(mbar), "r"(parity) : "memory");
    if (!done) {
        asm volatile(
            "{ .reg .pred P1;\n"
            "W%=:\n"
            "mbarrier.try_wait.parity.acquire.cta.shared::cta.b64 P1, [%0], %1, 0x989680;\n"
            "@P1 bra.uni D%=;\n"
            "bra.uni W%=;\n"
            "D%=: }"
            :: "r"(mbar), "r"(parity) : "memory");
    }
}
__device__ __forceinline__ void bulk_g2s(uint32_t dst, const void* src, uint32_t bytes, uint32_t mbar) {
    asm volatile(
        "cp.async.bulk.shared::cluster.global.mbarrier::complete_tx::bytes [%0], [%1], %2, [%3];"
        :: "r"(dst), "l"(src), "r"(bytes), "r"(mbar) : "memory");
}

// K1: zero degree array + int64/int32 detection
__global__ void prep_zero_detect(const int* __restrict__ raw) {
    int i = blockIdx.x * blockDim.x + threadIdx.x;
    if (i < NUM_SRC) g_deg[i] = 0;
    if (blockIdx.x == 0 && threadIdx.x < 32) {
        int bad = 0;
        #pragma unroll
        for (int u = 0; u < 16; u++)
            bad |= (raw[2 * (threadIdx.x * 16 + u) + 1] != 0);
        unsigned m = __ballot_sync(0xffffffffu, bad);
        if (threadIdx.x == 0) g_is64 = (m == 0u);
    }
}

// K2: normalize indices + degree histogram + direct use-list fill
__global__ void prep_convert_hist_fill(const void* __restrict__ raw) {
    int t = blockIdx.x * blockDim.x + threadIdx.x;
    if (t < TOTAL_IDX) {
        int v;
        if (g_is64) v = (int)((const long long*)raw)[t];
        else        v = ((const int*)raw)[t];
        g_idx[t] = v;
        int pos = atomicAdd(&g_deg[v], 1);
        if (pos < USE_CAP) g_uses[v * USE_CAP + pos] = t;
    }
}

// K3: triple-buffered TMA row streamer @512 threads (cheaper per-row barrier).
//     Warp 15 prefetches the next row's use list; all 16 warps gather.
__global__ __launch_bounds__(512) void row_gather_pipe(const float* __restrict__ table) {
    extern __shared__ __align__(1024) unsigned char smem_raw[];
    const uint32_t base = smem_u32(smem_raw);
    int*  s_uses = (int*)(smem_raw + 64);
    int*  s_n    = (int*)(smem_raw + 64 + 2 * USE_CAP * 4);
    uint32_t mbar[NSTAGE], bufadr[NSTAGE];
    float* bufs[NSTAGE];
    #pragma unroll
    for (int s = 0; s < NSTAGE; s++) {
        mbar[s]   = base + 8 * s;
        bufadr[s] = base + 1024 + s * ROW_BYTES;
        bufs[s]   = (float*)(smem_raw + 1024 + s * ROW_BYTES);
    }

    const int tid  = threadIdx.x;
    const int wid  = tid >> 5;
    const int lane = tid & 31;

    if (tid == 0) {
        #pragma unroll
        for (int s = 0; s < NSTAGE; s++) mbar_init(mbar[s], 1);
    }
    __syncthreads();

    if (tid == 0) {
        #pragma unroll
        for (int p = 0; p < 2; p++) {
            int r = blockIdx.x + p * PIPE_GRID;
            if (r < NUM_SRC) {
                mbar_expect_tx(mbar[p], ROW_BYTES);
                #pragma unroll
                for (int c = 0; c < 4; c++)
                    bulk_g2s(bufadr[p] + c * (ROW_BYTES / 4),
                             (const char*)(table + (size_t)r * NUM_SRC) + c * (ROW_BYTES / 4),
                             ROW_BYTES / 4, mbar[p]);
            }
        }
    }
    if (wid == 0) {
        int r = blockIdx.x;
        int d = g_deg[r]; if (d > USE_CAP) d = USE_CAP;
        if (lane == 0) s_n[0] = d;
        for (int u = lane; u < d; u += 32) s_uses[u] = g_uses[r * USE_CAP + u];
    }
    __syncthreads();

    int ph[NSTAGE] = {0, 0, 0};
    int i = 0;
    for (int row = blockIdx.x; row < NUM_SRC; row += PIPE_GRID, i++) {
        const int st   = i % NSTAGE;
        const int slot = i & 1;

        int nxt2 = row + 2 * PIPE_GRID;
        if (nxt2 < NUM_SRC && tid == 0) {
            int ns = (i + 2) % NSTAGE;
            mbar_expect_tx(mbar[ns], ROW_BYTES);
            #pragma unroll
            for (int c = 0; c < 4; c++)
                bulk_g2s(bufadr[ns] + c * (ROW_BYTES / 4),
                         (const char*)(table + (size_t)nxt2 * NUM_SRC) + c * (ROW_BYTES / 4),
                         ROW_BYTES / 4, mbar[ns]);
        }

        if (wid == PIPE_WARPS - 1) {
            int r = row + PIPE_GRID;
            int d = 0;
            if (r < NUM_SRC) { d = g_deg[r]; if (d > USE_CAP) d = USE_CAP; }
            if (lane == 0) s_n[slot ^ 1] = d;
            for (int u = lane; u < d; u += 32)
                s_uses[(slot ^ 1) * USE_CAP + u] = g_uses[r * USE_CAP + u];
        }

        mbar_wait(mbar[st], ph[st]);
        ph[st] ^= 1;
        const float* srow = bufs[st];

        const int n = s_n[slot];
        for (int u = wid; u < n; u += PIPE_WARPS) {
            int t   = s_uses[slot * USE_CAP + u];
            int bse = t - (t % N_NBR);
            float* out = &g_tile[(size_t)t * WPITCH];   // pitch-52 row
            if (lane < N_NBR) {
                out[lane] = srow[g_idx[bse + lane]];
                int j = lane + 32;
                if (j < N_NBR) out[j] = srow[g_idx[bse + j]];
            }
        }
        __syncthreads();
    }
}

// K4: greedy — R15 version (REDUX argmax, straight float4 copy). 47.7us proven.
__global__ __launch_bounds__(128, 5) void dgrec_greedy_kernel(
    const float* __restrict__ h_src,
    float* __restrict__ out)
{
    __shared__ __align__(16) float sm[4 * W_STRIDE];   // 43008 B

    const int w    = threadIdx.x >> 5;
    const int lane = threadIdx.x & 31;
    const int b    = blockIdx.x * 4 + w;

    float* s     = &sm[w * W_STRIDE];
    float* cache = &sm[w * W_STRIDE + W_CACHE];
    int*   sels  = (int*)&sm[w * W_STRIDE + W_SELS];
    int*   sidx  = (int*)&sm[w * W_STRIDE + W_SIDX];
    float* nrmk  = &sm[w * W_STRIDE + W_NRMK];

    {
        const float4* tsrc4 = (const float4*)(g_tile + (size_t)b * N_NBR * WPITCH);
        float4* sdst4 = (float4*)s;
        #pragma unroll
        for (int q = 0; q < 20; q++)
            sdst4[lane + q * 32] = tsrc4[lane + q * 32];
        if (lane < 10) sdst4[lane + 640] = tsrc4[lane + 640];
        cache[lane] = 0.0f;
        if (lane < 20) cache[lane + 32] = 0.0f;
    }
    __syncwarp();

    const int row0   = lane;
    const int row1   = lane + 32;
    const bool has1  = (row1 < N_NBR);
    const float4* s1 = (const float4*)&s[(has1 ? row1 : row0) * WPITCH];
    const float4* c4 = (const float4*)cache;

    float4 r0[12];
    float  r48, r49;
    {
        const float4* s0 = (const float4*)&s[row0 * WPITCH];
        #pragma unroll
        for (int q = 0; q < 12; q++) r0[q] = s0[q];
        r48 = s[row0 * WPITCH + 48];
        r49 = s[row0 * WPITCH + 49];
    }

    for (int k = 0; k < K_SEL; k++) {
        float g0a = 0.f, g0b = 0.f, g0c = 0.f, g0d = 0.f;
        float g1a = 0.f, g1b = 0.f, g1c = 0.f, g1d = 0.f;
        #pragma unroll
        for (int q = 0; q < 12; q += 4) {
            float4 ca = c4[q],     aa = r0[q],     da = s1[q];
            float4 cb = c4[q + 1], ab = r0[q + 1], db = s1[q + 1];
            float4 cc = c4[q + 2], ac = r0[q + 2], dc = s1[q + 2];
            float4 cd = c4[q + 3], ad = r0[q + 3], dd = s1[q + 3];
            g0a += fmaxf(aa.x - ca.x, 0.f); g0a += fmaxf(aa.y - ca.y, 0.f);
            g0a += fmaxf(aa.z - ca.z, 0.f); g0a += fmaxf(aa.w - ca.w, 0.f);
            g0b += fmaxf(ab.x - cb.x, 0.f); g0b += fmaxf(ab.y - cb.y, 0.f);
            g0b += fmaxf(ab.z - cb.z, 0.f); g0b += fmaxf(ab.w - cb.w, 0.f);
            g0c += fmaxf(ac.x - cc.x, 0.f); g0c += fmaxf(ac.y - cc.y, 0.f);
            g0c += fmaxf(ac.z - cc.z, 0.f); g0c += fmaxf(ac.w - cc.w, 0.f);
            g0d += fmaxf(ad.x - cd.x, 0.f); g0d += fmaxf(ad.y - cd.y, 0.f);
            g0d += fmaxf(ad.z - cd.z, 0.f); g0d += fmaxf(ad.w - cd.w, 0.f);
            g1a += fmaxf(da.x - ca.x, 0.f); g1a += fmaxf(da.y - ca.y, 0.f);
            g1a += fmaxf(da.z - ca.z, 0.f); g1a += fmaxf(da.w - ca.w, 0.f);
            g1b += fmaxf(db.x - cb.x, 0.f); g1b += fmaxf(db.y - cb.y, 0.f);
            g1b += fmaxf(db.z - cb.z, 0.f); g1b += fmaxf(db.w - cb.w, 0.f);
            g1c += fmaxf(dc.x - cc.x, 0.f); g1c += fmaxf(dc.y - cc.y, 0.f);
            g1c += fmaxf(dc.z - cc.z, 0.f); g1c += fmaxf(dc.w - cc.w, 0.f);
            g1d += fmaxf(dd.x - cd.x, 0.f); g1d += fmaxf(dd.y - cd.y, 0.f);
            g1d += fmaxf(dd.z - cd.z, 0.f); g1d += fmaxf(dd.w - cd.w, 0.f);
        }
        {
            float c48 = cache[48], c49 = cache[49];
            g0a += fmaxf(r48 - c48, 0.f);
            g0b += fmaxf(r49 - c49, 0.f);
            g1a += fmaxf(s[(has1 ? row1 : row0) * WPITCH + 48] - c48, 0.f);
            g1b += fmaxf(s[(has1 ? row1 : row0) * WPITCH + 49] - c49, 0.f);
        }
        float g0 = (g0a + g0b) + (g0c + g0d);
        float g1 = (g1a + g1b) + (g1c + g1d);

        unsigned b0 = __float_as_uint(g0);
        unsigned b1 = has1 ? __float_as_uint(g1) : 0u;
        unsigned m0 = __reduce_max_sync(0xffffffffu, b0);
        unsigned m1 = __reduce_max_sync(0xffffffffu, b1);
        int sel;
        if (m1 > m0) {
            unsigned ball = __ballot_sync(0xffffffffu, has1 && (b1 == m1));
            sel = (__ffs(ball) - 1) + 32;
        } else {
            unsigned ball = __ballot_sync(0xffffffffu, b0 == m0);
            sel = __ffs(ball) - 1;
        }
        if (lane == 0) sels[k] = sel;

        const float* srw = &s[sel * WPITCH];
        cache[lane] = fmaxf(cache[lane], srw[lane]);
        if (has1) cache[row1] = fmaxf(cache[row1], srw[row1]);
        __syncwarp();
    }

    if (lane < K_SEL) {
        int idx2 = g_idx[b * N_NBR + sels[lane]];
        sidx[lane] = idx2;
        int d = g_deg[idx2];
        if (d < 1) d = 1;
        nrmk[lane] = rsqrtf((float)d);
    }
    __syncwarp();

    float acc0 = 0.0f, acc1 = 0.0f;
    #pragma unroll
    for (int k = 0; k < K_SEL; k++) {
        const float* hr = &h_src[(size_t)sidx[k] * D_FEAT];
        float nk = nrmk[k];
        acc0 += hr[lane]      * nk;
        acc1 += hr[lane + 32] * nk;
    }
    out[(size_t)b * D_FEAT + lane]      = acc0 * 0.1414213562373095f;
    out[(size_t)b * D_FEAT + lane + 32] = acc1 * 0.1414213562373095f;
}

extern "C" void kernel_launch(void* const* d_in, const int* in_sizes, int n_in,
                              void* d_out, int out_size) {
    const float* h_src = nullptr;
    const float* table = nullptr;
    const void*  nbrs  = nullptr;
    for (int i = 0; i < n_in; i++) {
        long long sz = in_sizes[i];
        if (sz == (long long)NUM_SRC * NUM_SRC)      table = (const float*)d_in[i];
        else if (sz == (long long)NUM_SRC * D_FEAT)  h_src = (const float*)d_in[i];
        else if (sz == (long long)TOTAL_IDX)         nbrs  = d_in[i];
    }
    float* out = (float*)d_out;

    const int smem_bytes = 1024 + NSTAGE * ROW_BYTES;
    cudaFuncSetAttribute(row_gather_pipe, cudaFuncAttributeMaxDynamicSharedMemorySize,
                         smem_bytes);

    prep_zero_detect<<<(NUM_SRC + 255) / 256, 256>>>((const int*)nbrs);
    prep_convert_hist_fill<<<(TOTAL_IDX + 255) / 256, 256>>>(nbrs);
    row_gather_pipe<<<PIPE_GRID, 512, smem_bytes>>>(table);
    dgrec_greedy_kernel<<<NUM_DST / 4, 128>>>(h_src, out);
}

// round 17
// speedup vs baseline: 1.1350x; 1.1350x over previous
#include <cuda_runtime.h>
#include <cstdint>

#define NUM_SRC 16384
#define NUM_DST 8192
#define N_NBR 50
#define D_FEAT 64
#define K_SEL 10
#define TOTAL_IDX (NUM_DST * N_NBR)
#define PIPE_GRID 152
#define ROW_BYTES (NUM_SRC * 4)   // 64 KB
#define NSTAGE 3
#define USE_CAP 96

#define WPITCH 52
#define W_TILE 2600
#define W_CACHE (W_TILE)
#define W_SELS  (W_TILE + 56)
#define W_SIDX  (W_TILE + 66)
#define W_NRMK  (W_TILE + 76)
#define W_STRIDE 2688               // floats, 10752 B

__device__ int   g_deg[NUM_SRC];
__device__ int   g_idx[TOTAL_IDX];
__device__ int   g_uses[NUM_SRC * USE_CAP];
__device__ float g_tile[(size_t)NUM_DST * N_NBR * WPITCH];  // 85 MB, pitch-52 tiles
__device__ int   g_is64;

__device__ __forceinline__ uint32_t smem_u32(const void* p) {
    uint32_t a;
    asm("{ .reg .u64 t; cvta.to.shared.u64 t, %1; cvt.u32.u64 %0, t; }" : "=r"(a) : "l"(p));
    return a;
}
__device__ __forceinline__ void mbar_init(uint32_t mbar, uint32_t cnt) {
    asm volatile("mbarrier.init.shared.b64 [%0], %1;" :: "r"(mbar), "r"(cnt) : "memory");
}
__device__ __forceinline__ void mbar_expect_tx(uint32_t mbar, uint32_t bytes) {
    asm volatile("mbarrier.arrive.expect_tx.shared.b64 _, [%0], %1;" :: "r"(mbar), "r"(bytes) : "memory");
}
__device__ __forceinline__ void mbar_wait(uint32_t mbar, uint32_t parity) {
    uint32_t done;
    asm volatile(
        "{ .reg .pred p;\n"
        "mbarrier.try_wait.parity.acquire.cta.shared::cta.b64 p, [%1], %2;\n"
        "selp.b32 %0, 1, 0, p; }"
        : "=r"(done) : "r"(mbar), "r"(parity) : "memory");
    if (!done) {
        asm volatile(
            "{ .reg .pred P1;\n"
            "W%=:\n"
            "mbarrier.try_wait.parity.acquire.cta.shared::cta.b64 P1, [%0], %1, 0x989680;\n"
            "@P1 bra.uni D%=;\n"
            "bra.uni W%=;\n"
            "D%=: }"
            :: "r"(mbar), "r"(parity) : "memory");
    }
}
// table reads are strictly streaming: evict_first so tile writes stay in L2
__device__ __forceinline__ void bulk_g2s_ef(uint32_t dst, const void* src, uint32_t bytes, uint32_t mbar) {
    uint64_t pol;
    asm volatile("createpolicy.fractional.L2::evict_first.b64 %0, 1.0;" : "=l"(pol));
    asm volatile(
        "cp.async.bulk.shared::cluster.global.L2::cache_hint.mbarrier::complete_tx::bytes "
        "[%0], [%1], %2, [%3], %4;"
        :: "r"(dst), "l"(src), "r"(bytes), "r"(mbar), "l"(pol) : "memory");
}

// K1: zero degree array + int64/int32 detection
__global__ void prep_zero_detect(const int* __restrict__ raw) {
    int i = blockIdx.x * blockDim.x + threadIdx.x;
    if (i < NUM_SRC) g_deg[i] = 0;
    if (blockIdx.x == 0 && threadIdx.x < 32) {
        int bad = 0;
        #pragma unroll
        for (int u = 0; u < 16; u++)
            bad |= (raw[2 * (threadIdx.x * 16 + u) + 1] != 0);
        unsigned m = __ballot_sync(0xffffffffu, bad);
        if (threadIdx.x == 0) g_is64 = (m == 0u);
    }
}

// K2: normalize indices + degree histogram + direct use-list fill
__global__ void prep_convert_hist_fill(const void* __restrict__ raw) {
    int t = blockIdx.x * blockDim.x + threadIdx.x;
    if (t < TOTAL_IDX) {
        int v;
        if (g_is64) v = (int)((const long long*)raw)[t];
        else        v = ((const int*)raw)[t];
        g_idx[t] = v;
        int pos = atomicAdd(&g_deg[v], 1);
        if (pos < USE_CAP) g_uses[v * USE_CAP + pos] = t;
    }
}

// K3: R15 pipe (1024 threads, triple-buffered TMA) + evict_first table reads.
__global__ __launch_bounds__(1024) void row_gather_pipe(const float* __restrict__ table) {
    extern __shared__ __align__(1024) unsigned char smem_raw[];
    const uint32_t base = smem_u32(smem_raw);
    int*  s_uses = (int*)(smem_raw + 64);
    int*  s_n    = (int*)(smem_raw + 64 + 2 * USE_CAP * 4);
    uint32_t mbar[NSTAGE], bufadr[NSTAGE];
    float* bufs[NSTAGE];
    #pragma unroll
    for (int s = 0; s < NSTAGE; s++) {
        mbar[s]   = base + 8 * s;
        bufadr[s] = base + 1024 + s * ROW_BYTES;
        bufs[s]   = (float*)(smem_raw + 1024 + s * ROW_BYTES);
    }

    const int tid  = threadIdx.x;
    const int wid  = tid >> 5;
    const int lane = tid & 31;

    if (tid == 0) {
        #pragma unroll
        for (int s = 0; s < NSTAGE; s++) mbar_init(mbar[s], 1);
    }
    __syncthreads();

    if (tid == 0) {
        #pragma unroll
        for (int p = 0; p < 2; p++) {
            int r = blockIdx.x + p * PIPE_GRID;
            if (r < NUM_SRC) {
                mbar_expect_tx(mbar[p], ROW_BYTES);
                #pragma unroll
                for (int c = 0; c < 4; c++)
                    bulk_g2s_ef(bufadr[p] + c * (ROW_BYTES / 4),
                                (const char*)(table + (size_t)r * NUM_SRC) + c * (ROW_BYTES / 4),
                                ROW_BYTES / 4, mbar[p]);
            }
        }
    }
    if (wid == 0) {
        int r = blockIdx.x;
        int d = g_deg[r]; if (d > USE_CAP) d = USE_CAP;
        if (lane == 0) s_n[0] = d;
        for (int u = lane; u < d; u += 32) s_uses[u] = g_uses[r * USE_CAP + u];
    }
    __syncthreads();

    int ph[NSTAGE] = {0, 0, 0};
    int i = 0;
    for (int row = blockIdx.x; row < NUM_SRC; row += PIPE_GRID, i++) {
        const int st   = i % NSTAGE;
        const int slot = i & 1;

        int nxt2 = row + 2 * PIPE_GRID;
        if (nxt2 < NUM_SRC && tid == 0) {
            int ns = (i + 2) % NSTAGE;
            mbar_expect_tx(mbar[ns], ROW_BYTES);
            #pragma unroll
            for (int c = 0; c < 4; c++)
                bulk_g2s_ef(bufadr[ns] + c * (ROW_BYTES / 4),
                            (const char*)(table + (size_t)nxt2 * NUM_SRC) + c * (ROW_BYTES / 4),
                            ROW_BYTES / 4, mbar[ns]);
        }

        if (wid == 31) {
            int r = row + PIPE_GRID;
            int d = 0;
            if (r < NUM_SRC) { d = g_deg[r]; if (d > USE_CAP) d = USE_CAP; }
            if (lane == 0) s_n[slot ^ 1] = d;
            for (int u = lane; u < d; u += 32)
                s_uses[(slot ^ 1) * USE_CAP + u] = g_uses[r * USE_CAP + u];
        }

        mbar_wait(mbar[st], ph[st]);
        ph[st] ^= 1;
        const float* srow = bufs[st];

        const int n = s_n[slot];
        for (int u = wid; u < n; u += 32) {
            int t   = s_uses[slot * USE_CAP + u];
            int bse = t - (t % N_NBR);
            float* out = &g_tile[(size_t)t * WPITCH];   // pitch-52 row
            if (lane < N_NBR) {
                out[lane] = srow[g_idx[bse + lane]];
                int j = lane + 32;
                if (j < N_NBR) out[j] = srow[g_idx[bse + j]];
            }
        }
        __syncthreads();
    }
}

// K4: greedy — R15 version (REDUX argmax, straight float4 copy). 47.7us proven.
__global__ __launch_bounds__(128, 5) void dgrec_greedy_kernel(
    const float* __restrict__ h_src,
    float* __restrict__ out)
{
    __shared__ __align__(16) float sm[4 * W_STRIDE];   // 43008 B

    const int w    = threadIdx.x >> 5;
    const int lane = threadIdx.x & 31;
    const int b    = blockIdx.x * 4 + w;

    float* s     = &sm[w * W_STRIDE];
    float* cache = &sm[w * W_STRIDE + W_CACHE];
    int*   sels  = (int*)&sm[w * W_STRIDE + W_SELS];
    int*   sidx  = (int*)&sm[w * W_STRIDE + W_SIDX];
    float* nrmk  = &sm[w * W_STRIDE + W_NRMK];

    {
        const float4* tsrc4 = (const float4*)(g_tile + (size_t)b * N_NBR * WPITCH);
        float4* sdst4 = (float4*)s;
        #pragma unroll
        for (int q = 0; q < 20; q++)
            sdst4[lane + q * 32] = tsrc4[lane + q * 32];
        if (lane < 10) sdst4[lane + 640] = tsrc4[lane + 640];
        cache[lane] = 0.0f;
        if (lane < 20) cache[lane + 32] = 0.0f;
    }
    __syncwarp();

    const int row0   = lane;
    const int row1   = lane + 32;
    const bool has1  = (row1 < N_NBR);
    const float4* s1 = (const float4*)&s[(has1 ? row1 : row0) * WPITCH];
    const float4* c4 = (const float4*)cache;

    float4 r0[12];
    float  r48, r49;
    {
        const float4* s0 = (const float4*)&s[row0 * WPITCH];
        #pragma unroll
        for (int q = 0; q < 12; q++) r0[q] = s0[q];
        r48 = s[row0 * WPITCH + 48];
        r49 = s[row0 * WPITCH + 49];
    }

    for (int k = 0; k < K_SEL; k++) {
        float g0a = 0.f, g0b = 0.f, g0c = 0.f, g0d = 0.f;
        float g1a = 0.f, g1b = 0.f, g1c = 0.f, g1d = 0.f;
        #pragma unroll
        for (int q = 0; q < 12; q += 4) {
            float4 ca = c4[q],     aa = r0[q],     da = s1[q];
            float4 cb = c4[q + 1], ab = r0[q + 1], db = s1[q + 1];
            float4 cc = c4[q + 2], ac = r0[q + 2], dc = s1[q + 2];
            float4 cd = c4[q + 3], ad = r0[q + 3], dd = s1[q + 3];
            g0a += fmaxf(aa.x - ca.x, 0.f); g0a += fmaxf(aa.y - ca.y, 0.f);
            g0a += fmaxf(aa.z - ca.z, 0.f); g0a += fmaxf(aa.w - ca.w, 0.f);
            g0b += fmaxf(ab.x - cb.x, 0.f); g0b += fmaxf(ab.y - cb.y, 0.f);
            g0b += fmaxf(ab.z - cb.z, 0.f); g0b += fmaxf(ab.w - cb.w, 0.f);
            g0c += fmaxf(ac.x - cc.x, 0.f); g0c += fmaxf(ac.y - cc.y, 0.f);
            g0c += fmaxf(ac.z - cc.z, 0.f); g0c += fmaxf(ac.w - cc.w, 0.f);
            g0d += fmaxf(ad.x - cd.x, 0.f); g0d += fmaxf(ad.y - cd.y, 0.f);
            g0d += fmaxf(ad.z - cd.z, 0.f); g0d += fmaxf(ad.w - cd.w, 0.f);
            g1a += fmaxf(da.x - ca.x, 0.f); g1a += fmaxf(da.y - ca.y, 0.f);
            g1a += fmaxf(da.z - ca.z, 0.f); g1a += fmaxf(da.w - ca.w, 0.f);
            g1b += fmaxf(db.x - cb.x, 0.f); g1b += fmaxf(db.y - cb.y, 0.f);
            g1b += fmaxf(db.z - cb.z, 0.f); g1b += fmaxf(db.w - cb.w, 0.f);
            g1c += fmaxf(dc.x - cc.x, 0.f); g1c += fmaxf(dc.y - cc.y, 0.f);
            g1c += fmaxf(dc.z - cc.z, 0.f); g1c += fmaxf(dc.w - cc.w, 0.f);
            g1d += fmaxf(dd.x - cd.x, 0.f); g1d += fmaxf(dd.y - cd.y, 0.f);
            g1d += fmaxf(dd.z - cd.z, 0.f); g1d += fmaxf(dd.w - cd.w, 0.f);
        }
        {
            float c48 = cache[48], c49 = cache[49];
            g0a += fmaxf(r48 - c48, 0.f);
            g0b += fmaxf(r49 - c49, 0.f);
            g1a += fmaxf(s[(has1 ? row1 : row0) * WPITCH + 48] - c48, 0.f);
            g1b += fmaxf(s[(has1 ? row1 : row0) * WPITCH + 49] - c49, 0.f);
        }
        float g0 = (g0a + g0b) + (g0c + g0d);
        float g1 = (g1a + g1b) + (g1c + g1d);

        unsigned b0 = __float_as_uint(g0);
        unsigned b1 = has1 ? __float_as_uint(g1) : 0u;
        unsigned m0 = __reduce_max_sync(0xffffffffu, b0);
        unsigned m1 = __reduce_max_sync(0xffffffffu, b1);
        int sel;
        if (m1 > m0) {
            unsigned ball = __ballot_sync(0xffffffffu, has1 && (b1 == m1));
            sel = (__ffs(ball) - 1) + 32;
        } else {
            unsigned ball = __ballot_sync(0xffffffffu, b0 == m0);
            sel = __ffs(ball) - 1;
        }
        if (lane == 0) sels[k] = sel;

        const float* srw = &s[sel * WPITCH];
        cache[lane] = fmaxf(cache[lane], srw[lane]);
        if (has1) cache[row1] = fmaxf(cache[row1], srw[row1]);
        __syncwarp();
    }

    if (lane < K_SEL) {
        int idx2 = g_idx[b * N_NBR + sels[lane]];
        sidx[lane] = idx2;
        int d = g_deg[idx2];
        if (d < 1) d = 1;
        nrmk[lane] = rsqrtf((float)d);
    }
    __syncwarp();

    float acc0 = 0.0f, acc1 = 0.0f;
    #pragma unroll
    for (int k = 0; k < K_SEL; k++) {
        const float* hr = &h_src[(size_t)sidx[k] * D_FEAT];
        float nk = nrmk[k];
        acc0 += hr[lane]      * nk;
        acc1 += hr[lane + 32] * nk;
    }
    out[(size_t)b * D_FEAT + lane]      = acc0 * 0.1414213562373095f;
    out[(size_t)b * D_FEAT + lane + 32] = acc1 * 0.1414213562373095f;
}

extern "C" void kernel_launch(void* const* d_in, const int* in_sizes, int n_in,
                              void* d_out, int out_size) {
    const float* h_src = nullptr;
    const float* table = nullptr;
    const void*  nbrs  = nullptr;
    for (int i = 0; i < n_in; i++) {
        long long sz = in_sizes[i];
        if (sz == (long long)NUM_SRC * NUM_SRC)      table = (const float*)d_in[i];
        else if (sz == (long long)NUM_SRC * D_FEAT)  h_src = (const float*)d_in[i];
        else if (sz == (long long)TOTAL_IDX)         nbrs  = d_in[i];
    }
    float* out = (float*)d_out;

    const int smem_bytes = 1024 + NSTAGE * ROW_BYTES;
    cudaFuncSetAttribute(row_gather_pipe, cudaFuncAttributeMaxDynamicSharedMemorySize,
                         smem_bytes);

    prep_zero_detect<<<(NUM_SRC + 255) / 256, 256>>>((const int*)nbrs);
    prep_convert_hist_fill<<<(TOTAL_IDX + 255) / 256, 256>>>(nbrs);
    row_gather_pipe<<<PIPE_GRID, 1024, smem_bytes>>>(table);
    dgrec_greedy_kernel<<<NUM_DST / 4, 128>>>(h_src, out);
}